// round 1
// baseline (speedup 1.0000x reference)
#include <cuda_runtime.h>

#define NROWS 65536
#define XD    362
#define NA    3
#define TILE  64
#define NT    (NROWS / TILE)   // 1024 tiles per action bucket (worst case)

// Scratch (device globals: allocation-free rule). Unwritten slots stay zero forever.
__device__ float  g_att  [(size_t)NA * NROWS * 6];
__device__ float  g_delta[(size_t)NA * NROWS * 6];
__device__ int    g_cnt[NA];
__device__ double g_acc;

__global__ void k_init() {
    int t = threadIdx.x;
    if (t < NA) g_cnt[t] = 0;
    if (t == 0) g_acc = 0.0;
}

// One warp per row: find sentinel (first index where x==10.0f), gather the 6
// attended cells from x and next, scatter (att, next-att) into the action bucket.
__global__ void k_prep(const float* __restrict__ x, const float* __restrict__ nx,
                       const int* __restrict__ act) {
    int w    = (blockIdx.x * blockDim.x + threadIdx.x) >> 5;
    int lane = threadIdx.x & 31;
    if (w >= NROWS) return;
    const float* xr = x + (size_t)w * XD;

    int found = 0x7fffffff;
    for (int base = 0; base < XD; base += 32) {
        int i = base + lane;
        float v = (i < XD) ? __ldg(xr + i) : 0.f;
        bool hit = (v == 10.0f);
        if (hit) found = i;
        if (__ballot_sync(0xffffffffu, hit)) break;   // early exit: ~halves scan
    }
    #pragma unroll
    for (int off = 16; off; off >>= 1)
        found = min(found, __shfl_xor_sync(0xffffffffu, found, off));
    int p = found;
    if (p < 19 || p >= XD - 19) p = 20;   // safety clamp; reference guarantees in-range

    int a = act[w];
    int slot = 0;
    if (lane == 0) slot = atomicAdd(&g_cnt[a], 1);
    slot = __shfl_sync(0xffffffffu, slot, 0);

    if (lane < 6) {
        int idx = 0;
        if      (lane == 1) idx = p;
        else if (lane == 2) idx = p - 19;
        else if (lane == 3) idx = p + 19;
        else if (lane == 4) idx = p - 1;
        else if (lane == 5) idx = p + 1;
        float av = xr[idx];
        float nv = nx[(size_t)w * XD + idx];
        size_t o = ((size_t)a * NROWS + (size_t)slot) * 6 + lane;
        g_att[o]   = av;
        g_delta[o] = nv - av;
    }
}

// Fused 4-layer expert MLP + MSE partial reduction. One 64-row single-action
// tile per block, 256 threads. Activations live transposed in smem
// (h1T[100][64], h2T[400][64]); W2/W3 stream from L2 via float4 LDG.
__global__ __launch_bounds__(256, 1)
void k_mlp(const float* __restrict__ W1, const float* __restrict__ b1,
           const float* __restrict__ W2, const float* __restrict__ b2,
           const float* __restrict__ W3, const float* __restrict__ b3,
           const float* __restrict__ W4, const float* __restrict__ b4) {
    extern __shared__ float sm[];
    float* h2T  = sm;                    // [400][64]   102400 B
    float* h1T  = h2T + 400 * 64;        // [100][64]    25600 B (reused as h3T)
    float* sX   = h1T + 100 * 64;        // [64][6]
    float* sD   = sX + TILE * 6;         // [64][6]
    float* sW1  = sD + TILE * 6;         // [6][100]
    float* sB1  = sW1 + 600;             // [100]
    float* sB2  = sB1 + 100;             // [400]
    float* sB3  = sB2 + 400;             // [100]
    float* sW4  = sB3 + 100;             // [100][6]
    float* sB4  = sW4 + 600;             // [8]
    float* sRed = sB4 + 8;               // [8]

    const int a    = blockIdx.x / NT;
    const int t    = blockIdx.x - a * NT;
    const int cnt  = g_cnt[a];
    const int row0 = t * TILE;
    if (row0 >= cnt) return;             // uniform per block
    const int nrows = min(TILE, cnt - row0);
    const int tid   = threadIdx.x;

    {   // stage inputs + small weights
        const float* gA = g_att   + ((size_t)a * NROWS + row0) * 6;
        const float* gD = g_delta + ((size_t)a * NROWS + row0) * 6;
        for (int i = tid; i < TILE * 6; i += 256) {
            int r = i / 6;
            float xv = 0.f, dv = 0.f;
            if (r < nrows) { xv = gA[i]; dv = gD[i]; }
            sX[i] = xv; sD[i] = dv;
        }
        for (int i = tid; i < 600; i += 256) sW1[i] = W1[a * 600 + i];
        for (int i = tid; i < 600; i += 256) sW4[i] = W4[a * 600 + i];
        for (int i = tid; i < 400; i += 256) sB2[i] = b2[a * 400 + i];
        if (tid < 100) sB1[tid] = b1[a * 100 + tid];
        if (tid < 100) sB3[tid] = b3[a * 100 + tid];
        if (tid < 8)   sB4[tid] = (tid < 6) ? b4[a * 6 + tid] : 0.f;
    }
    __syncthreads();

    // ---- layer 1: h1T[c][r] = relu(X @ W1 + b1), K=6 (trivial) ----
    for (int o = tid; o < 100 * 64; o += 256) {
        int c = o >> 6, r = o & 63;
        float s = sB1[c];
        #pragma unroll
        for (int k = 0; k < 6; k++) s = fmaf(sX[r * 6 + k], sW1[k * 100 + c], s);
        h1T[o] = fmaxf(s, 0.f);
    }
    __syncthreads();

    const int tr = tid & 7;   // row group: rows tr*8 .. tr*8+7
    const int tc = tid >> 3;  // col group (0..31)

    // ---- layer 2: h2T[j][r] = relu(h1 @ W2 + b2), 64x400, K=100 ----
    {
        const float* W2a = W2 + a * 40000;
        for (int p = 0; p < 4; p++) {
            int j0 = p * 128 + tc * 4;
            if (j0 < 400) {
                float acc[8][4];
                #pragma unroll
                for (int i = 0; i < 8; i++)
                    #pragma unroll
                    for (int j = 0; j < 4; j++) acc[i][j] = 0.f;
                #pragma unroll 4
                for (int k = 0; k < 100; k++) {
                    float4 a0 = *(const float4*)(h1T + k * 64 + tr * 8);
                    float4 a1 = *(const float4*)(h1T + k * 64 + tr * 8 + 4);
                    float4 bv = *(const float4*)(W2a + k * 400 + j0);
                    float av[8] = {a0.x, a0.y, a0.z, a0.w, a1.x, a1.y, a1.z, a1.w};
                    float bw[4] = {bv.x, bv.y, bv.z, bv.w};
                    #pragma unroll
                    for (int i = 0; i < 8; i++)
                        #pragma unroll
                        for (int j = 0; j < 4; j++)
                            acc[i][j] = fmaf(av[i], bw[j], acc[i][j]);
                }
                #pragma unroll
                for (int j = 0; j < 4; j++) {
                    float bj = sB2[j0 + j];
                    float4 v0 = make_float4(fmaxf(acc[0][j] + bj, 0.f), fmaxf(acc[1][j] + bj, 0.f),
                                            fmaxf(acc[2][j] + bj, 0.f), fmaxf(acc[3][j] + bj, 0.f));
                    float4 v1 = make_float4(fmaxf(acc[4][j] + bj, 0.f), fmaxf(acc[5][j] + bj, 0.f),
                                            fmaxf(acc[6][j] + bj, 0.f), fmaxf(acc[7][j] + bj, 0.f));
                    *(float4*)(h2T + (j0 + j) * 64 + tr * 8)     = v0;
                    *(float4*)(h2T + (j0 + j) * 64 + tr * 8 + 4) = v1;
                }
            }
        }
    }
    __syncthreads();

    // ---- layer 3: h3T[i][r] = relu(h2 @ W3 + b3), 64x100, K=400 (into h1T) ----
    if (tc < 25) {
        const float* W3a = W3 + a * 40000;
        const int i0 = tc * 4;
        float acc[8][4];
        #pragma unroll
        for (int i = 0; i < 8; i++)
            #pragma unroll
            for (int j = 0; j < 4; j++) acc[i][j] = 0.f;
        #pragma unroll 4
        for (int k = 0; k < 400; k++) {
            float4 a0 = *(const float4*)(h2T + k * 64 + tr * 8);
            float4 a1 = *(const float4*)(h2T + k * 64 + tr * 8 + 4);
            float4 bv = *(const float4*)(W3a + k * 100 + i0);
            float av[8] = {a0.x, a0.y, a0.z, a0.w, a1.x, a1.y, a1.z, a1.w};
            float bw[4] = {bv.x, bv.y, bv.z, bv.w};
            #pragma unroll
            for (int i = 0; i < 8; i++)
                #pragma unroll
                for (int j = 0; j < 4; j++)
                    acc[i][j] = fmaf(av[i], bw[j], acc[i][j]);
        }
        #pragma unroll
        for (int j = 0; j < 4; j++) {
            float bj = sB3[i0 + j];
            float4 v0 = make_float4(fmaxf(acc[0][j] + bj, 0.f), fmaxf(acc[1][j] + bj, 0.f),
                                    fmaxf(acc[2][j] + bj, 0.f), fmaxf(acc[3][j] + bj, 0.f));
            float4 v1 = make_float4(fmaxf(acc[4][j] + bj, 0.f), fmaxf(acc[5][j] + bj, 0.f),
                                    fmaxf(acc[6][j] + bj, 0.f), fmaxf(acc[7][j] + bj, 0.f));
            *(float4*)(h1T + (i0 + j) * 64 + tr * 8)     = v0;
            *(float4*)(h1T + (i0 + j) * 64 + tr * 8 + 4) = v1;
        }
    }
    __syncthreads();

    // ---- layer 4 + squared-error accumulation: out 64x6, K=100 ----
    float local = 0.f;
    for (int o = tid; o < TILE * 6; o += 256) {
        int r = o & 63, c = o >> 6;
        float s = sB4[c];
        #pragma unroll 4
        for (int k = 0; k < 100; k++) s = fmaf(h1T[k * 64 + r], sW4[k * 6 + c], s);
        if (r < nrows) { float d = s - sD[r * 6 + c]; local += d * d; }
    }
    #pragma unroll
    for (int off = 16; off; off >>= 1) local += __shfl_xor_sync(0xffffffffu, local, off);
    if ((tid & 31) == 0) sRed[tid >> 5] = local;
    __syncthreads();
    if (tid == 0) {
        float s = 0.f;
        #pragma unroll
        for (int i = 0; i < 8; i++) s += sRed[i];
        atomicAdd(&g_acc, (double)s);
    }
}

__global__ void k_fin(float* out, int n) {
    float v = (float)(g_acc / ((double)NROWS * 6.0));
    for (int i = threadIdx.x; i < n; i += blockDim.x) out[i] = v;
}

extern "C" void kernel_launch(void* const* d_in, const int* in_sizes, int n_in,
                              void* d_out, int out_size) {
    const float* x  = (const float*)d_in[0];
    const float* nx = (const float*)d_in[1];
    const int*   ac = (const int*)d_in[2];
    const float* W1 = (const float*)d_in[3];
    const float* b1 = (const float*)d_in[4];
    const float* W2 = (const float*)d_in[5];
    const float* b2 = (const float*)d_in[6];
    const float* W3 = (const float*)d_in[7];
    const float* b3 = (const float*)d_in[8];
    const float* W4 = (const float*)d_in[9];
    const float* b4 = (const float*)d_in[10];

    const size_t smem =
        (size_t)(400 * 64 + 100 * 64 + TILE * 6 * 2 + 600 + 100 + 400 + 100 + 600 + 8 + 8)
        * sizeof(float);  // 138,336 B
    cudaFuncSetAttribute(k_mlp, cudaFuncAttributeMaxDynamicSharedMemorySize, (int)smem);

    k_init<<<1, 32>>>();
    k_prep<<<NROWS / 8, 256>>>(x, nx, ac);
    k_mlp<<<NA * NT, 256, smem>>>(W1, b1, W2, b2, W3, b3, W4, b4);
    k_fin<<<1, 64>>>((float*)d_out, out_size);
}

// round 2
// speedup vs baseline: 1.3515x; 1.3515x over previous
#include <cuda_runtime.h>

#define NROWS 65536
#define XD    362
#define NA    3
#define TILE  64
#define NT    (NROWS / TILE)   // 1024 tiles per action bucket (worst case)
#define NTHR  800              // 25 warps: 8 rowgrp x 100 colgrp = 800 slots

typedef unsigned long long u64t;

__device__ float  g_att  [(size_t)NA * NROWS * 6];
__device__ float  g_delta[(size_t)NA * NROWS * 6];
__device__ int    g_cnt[NA];
__device__ double g_acc;

__device__ __forceinline__ u64t dup2(float v) {
    u64t r; asm("mov.b64 %0, {%1, %1};" : "=l"(r) : "f"(v)); return r;
}
__device__ __forceinline__ void fma2(u64t& d, u64t a, u64t b) {
    asm("fma.rn.f32x2 %0, %1, %2, %0;" : "+l"(d) : "l"(a), "l"(b));
}
__device__ __forceinline__ float2 u2f(u64t u) {
    float2 f; asm("mov.b64 {%0, %1}, %2;" : "=f"(f.x), "=f"(f.y) : "l"(u)); return f;
}

__global__ void k_init() {
    int t = threadIdx.x;
    if (t < NA) g_cnt[t] = 0;
    if (t == 0) g_acc = 0.0;
}

// One warp per row: find sentinel, gather 6 cells, bucket-scatter by action.
__global__ void k_prep(const float* __restrict__ x, const float* __restrict__ nx,
                       const int* __restrict__ act) {
    int w    = (blockIdx.x * blockDim.x + threadIdx.x) >> 5;
    int lane = threadIdx.x & 31;
    if (w >= NROWS) return;
    const float* xr = x + (size_t)w * XD;

    int found = 0x7fffffff;
    for (int base = 0; base < XD; base += 32) {
        int i = base + lane;
        float v = (i < XD) ? __ldg(xr + i) : 0.f;
        bool hit = (v == 10.0f);
        if (hit) found = i;
        if (__ballot_sync(0xffffffffu, hit)) break;
    }
    #pragma unroll
    for (int off = 16; off; off >>= 1)
        found = min(found, __shfl_xor_sync(0xffffffffu, found, off));
    int p = found;
    if (p < 19 || p >= XD - 19) p = 20;

    int a = act[w];
    int slot = 0;
    if (lane == 0) slot = atomicAdd(&g_cnt[a], 1);
    slot = __shfl_sync(0xffffffffu, slot, 0);

    if (lane < 6) {
        int idx = 0;
        if      (lane == 1) idx = p;
        else if (lane == 2) idx = p - 19;
        else if (lane == 3) idx = p + 19;
        else if (lane == 4) idx = p - 1;
        else if (lane == 5) idx = p + 1;
        float av = xr[idx];
        float nv = nx[(size_t)w * XD + idx];
        size_t o = ((size_t)a * NROWS + (size_t)slot) * 6 + lane;
        g_att[o]   = av;
        g_delta[o] = nv - av;
    }
}

// Fused 4-layer expert MLP + MSE partials. 64-row single-action tile per block,
// 800 threads. FFMA2 (fp32x2) microkernels; layer-3 K-split 4-ways with
// partials parked in the (then dead) h2T region.
__global__ __launch_bounds__(NTHR, 1)
void k_mlp(const float* __restrict__ W1, const float* __restrict__ b1,
           const float* __restrict__ W2, const float* __restrict__ b2,
           const float* __restrict__ W3, const float* __restrict__ b3,
           const float* __restrict__ W4, const float* __restrict__ b4) {
    extern __shared__ float sm[];
    float* h2T  = sm;                    // [400][64]   102400 B (also layer-3 partials)
    float* h1T  = h2T + 400 * 64;        // [100][64]    25600 B (reused as h3T)
    float* sX   = h1T + 100 * 64;        // [64][6]
    float* sD   = sX + TILE * 6;         // [64][6]
    float* sW1  = sD + TILE * 6;         // [6][100]
    float* sB1  = sW1 + 600;             // [100]
    float* sB2  = sB1 + 100;             // [400]
    float* sB3  = sB2 + 400;             // [100]
    float* sW4  = sB3 + 100;             // [100][6]
    float* sB4  = sW4 + 600;             // [8]
    float* sRed = sB4 + 8;               // [32]

    const int a    = blockIdx.x / NT;
    const int t    = blockIdx.x - a * NT;
    const int cnt  = g_cnt[a];
    const int row0 = t * TILE;
    if (row0 >= cnt) return;
    const int nrows = min(TILE, cnt - row0);
    const int tid   = threadIdx.x;

    {   // stage inputs + small weights
        const float* gA = g_att   + ((size_t)a * NROWS + row0) * 6;
        const float* gD = g_delta + ((size_t)a * NROWS + row0) * 6;
        for (int i = tid; i < TILE * 6; i += NTHR) {
            int r = i / 6;
            float xv = 0.f, dv = 0.f;
            if (r < nrows) { xv = gA[i]; dv = gD[i]; }
            sX[i] = xv; sD[i] = dv;
        }
        for (int i = tid; i < 600; i += NTHR) sW1[i] = W1[a * 600 + i];
        for (int i = tid; i < 600; i += NTHR) sW4[i] = W4[a * 600 + i];
        for (int i = tid; i < 400; i += NTHR) sB2[i] = b2[a * 400 + i];
        if (tid < 100) sB1[tid] = b1[a * 100 + tid];
        if (tid < 100) sB3[tid] = b3[a * 100 + tid];
        if (tid < 8)   sB4[tid] = (tid < 6) ? b4[a * 6 + tid] : 0.f;
    }
    __syncthreads();

    // ---- layer 1: h1T[c][r] = relu(X @ W1 + b1), K=6 ----
    for (int o = tid; o < 100 * 64; o += NTHR) {
        int c = o >> 6, r = o & 63;
        float s = sB1[c];
        #pragma unroll
        for (int k = 0; k < 6; k++) s = fmaf(sX[r * 6 + k], sW1[k * 100 + c], s);
        h1T[o] = fmaxf(s, 0.f);
    }
    __syncthreads();

    // ---- layer 2: h2T[j][r] = relu(h1 @ W2 + b2), 64x400, K=100 ----
    // 800 slots = 8 rowgrps (8 rows) x 100 colgrps (4 cols) -> 100% utilization.
    {
        const int rg = tid & 7;        // rows rg*8 .. rg*8+7 (4 f32x2 pairs)
        const int cg = tid >> 3;       // cols cg*4 .. cg*4+3
        const int j0 = cg * 4;
        const float* W2a = W2 + a * 40000;
        u64t acc[4][4];
        #pragma unroll
        for (int i = 0; i < 4; i++)
            #pragma unroll
            for (int j = 0; j < 4; j++) acc[i][j] = 0ull;
        #pragma unroll 2
        for (int k = 0; k < 100; k++) {
            const u64t* ap = (const u64t*)(h1T + k * 64 + rg * 8);
            u64t a0 = ap[0], a1 = ap[1], a2 = ap[2], a3 = ap[3];
            float4 bv = *(const float4*)(W2a + k * 400 + j0);
            u64t b0 = dup2(bv.x), b1d = dup2(bv.y), b2d = dup2(bv.z), b3d = dup2(bv.w);
            fma2(acc[0][0], a0, b0);  fma2(acc[1][0], a1, b0);
            fma2(acc[2][0], a2, b0);  fma2(acc[3][0], a3, b0);
            fma2(acc[0][1], a0, b1d); fma2(acc[1][1], a1, b1d);
            fma2(acc[2][1], a2, b1d); fma2(acc[3][1], a3, b1d);
            fma2(acc[0][2], a0, b2d); fma2(acc[1][2], a1, b2d);
            fma2(acc[2][2], a2, b2d); fma2(acc[3][2], a3, b2d);
            fma2(acc[0][3], a0, b3d); fma2(acc[1][3], a1, b3d);
            fma2(acc[2][3], a2, b3d); fma2(acc[3][3], a3, b3d);
        }
        #pragma unroll
        for (int j = 0; j < 4; j++) {
            float bj = sB2[j0 + j];
            #pragma unroll
            for (int i = 0; i < 4; i++) {
                float2 f = u2f(acc[i][j]);
                f.x = fmaxf(f.x + bj, 0.f);
                f.y = fmaxf(f.y + bj, 0.f);
                *(float2*)(h2T + (j0 + j) * 64 + rg * 8 + 2 * i) = f;
            }
        }
    }
    __syncthreads();

    // ---- layer 3: h3 = relu(h2 @ W3 + b3), 64x100, K=400, 4-way K-split ----
    // 800 slots = 4 kgrps x (8 rowgrps x 25 colgrps). Partials -> h2T region.
    {
        const int kg  = tid / 200;
        const int rem = tid - kg * 200;
        const int rg  = rem & 7;
        const int cg  = rem >> 3;      // 0..24
        const int i0  = cg * 4;
        const float* W3a = W3 + a * 40000 + kg * 100 * 100;
        u64t acc[4][4];
        #pragma unroll
        for (int i = 0; i < 4; i++)
            #pragma unroll
            for (int j = 0; j < 4; j++) acc[i][j] = 0ull;
        #pragma unroll 2
        for (int k = 0; k < 100; k++) {
            const u64t* ap = (const u64t*)(h2T + (kg * 100 + k) * 64 + rg * 8);
            u64t a0 = ap[0], a1 = ap[1], a2 = ap[2], a3 = ap[3];
            float4 bv = *(const float4*)(W3a + k * 100 + i0);
            u64t b0 = dup2(bv.x), b1d = dup2(bv.y), b2d = dup2(bv.z), b3d = dup2(bv.w);
            fma2(acc[0][0], a0, b0);  fma2(acc[1][0], a1, b0);
            fma2(acc[2][0], a2, b0);  fma2(acc[3][0], a3, b0);
            fma2(acc[0][1], a0, b1d); fma2(acc[1][1], a1, b1d);
            fma2(acc[2][1], a2, b1d); fma2(acc[3][1], a3, b1d);
            fma2(acc[0][2], a0, b2d); fma2(acc[1][2], a1, b2d);
            fma2(acc[2][2], a2, b2d); fma2(acc[3][2], a3, b2d);
            fma2(acc[0][3], a0, b3d); fma2(acc[1][3], a1, b3d);
            fma2(acc[2][3], a2, b3d); fma2(acc[3][3], a3, b3d);
        }
        __syncthreads();   // all h2 reads done before overwriting with partials
        #pragma unroll
        for (int j = 0; j < 4; j++)
            #pragma unroll
            for (int i = 0; i < 4; i++)
                *(u64t*)(h2T + (kg * 100 + i0 + j) * 64 + rg * 8 + 2 * i) = acc[i][j];
    }
    __syncthreads();

    // reduce 4 K-partials + bias + relu -> h3T (in h1T region). 8 outputs/thread.
    {
        const int c  = tid >> 3;        // 0..99
        const int r0 = (tid & 7) * 8;
        float4 s0 = make_float4(0.f, 0.f, 0.f, 0.f), s1 = s0;
        #pragma unroll
        for (int kg = 0; kg < 4; kg++) {
            const float* p = h2T + (kg * 100 + c) * 64 + r0;
            float4 v0 = *(const float4*)p;
            float4 v1 = *(const float4*)(p + 4);
            s0.x += v0.x; s0.y += v0.y; s0.z += v0.z; s0.w += v0.w;
            s1.x += v1.x; s1.y += v1.y; s1.z += v1.z; s1.w += v1.w;
        }
        float bj = sB3[c];
        float4 o0 = make_float4(fmaxf(s0.x + bj, 0.f), fmaxf(s0.y + bj, 0.f),
                                fmaxf(s0.z + bj, 0.f), fmaxf(s0.w + bj, 0.f));
        float4 o1 = make_float4(fmaxf(s1.x + bj, 0.f), fmaxf(s1.y + bj, 0.f),
                                fmaxf(s1.z + bj, 0.f), fmaxf(s1.w + bj, 0.f));
        *(float4*)(h1T + c * 64 + r0)     = o0;
        *(float4*)(h1T + c * 64 + r0 + 4) = o1;
    }
    __syncthreads();

    // ---- layer 4 + squared-error accumulation: out 64x6, K=100 ----
    float local = 0.f;
    for (int o = tid; o < TILE * 6; o += NTHR) {
        int r = o & 63, c = o >> 6;
        float s = sB4[c];
        #pragma unroll 4
        for (int k = 0; k < 100; k++) s = fmaf(h1T[k * 64 + r], sW4[k * 6 + c], s);
        if (r < nrows) { float d = s - sD[r * 6 + c]; local += d * d; }
    }
    #pragma unroll
    for (int off = 16; off; off >>= 1) local += __shfl_xor_sync(0xffffffffu, local, off);
    if ((tid & 31) == 0) sRed[tid >> 5] = local;
    __syncthreads();
    if (tid == 0) {
        float s = 0.f;
        #pragma unroll
        for (int i = 0; i < 25; i++) s += sRed[i];
        atomicAdd(&g_acc, (double)s);
    }
}

__global__ void k_fin(float* out, int n) {
    float v = (float)(g_acc / ((double)NROWS * 6.0));
    for (int i = threadIdx.x; i < n; i += blockDim.x) out[i] = v;
}

extern "C" void kernel_launch(void* const* d_in, const int* in_sizes, int n_in,
                              void* d_out, int out_size) {
    const float* x  = (const float*)d_in[0];
    const float* nx = (const float*)d_in[1];
    const int*   ac = (const int*)d_in[2];
    const float* W1 = (const float*)d_in[3];
    const float* b1 = (const float*)d_in[4];
    const float* W2 = (const float*)d_in[5];
    const float* b2 = (const float*)d_in[6];
    const float* W3 = (const float*)d_in[7];
    const float* b3 = (const float*)d_in[8];
    const float* W4 = (const float*)d_in[9];
    const float* b4 = (const float*)d_in[10];

    const size_t smem =
        (size_t)(400 * 64 + 100 * 64 + TILE * 6 * 2 + 600 + 100 + 400 + 100 + 600 + 8 + 32)
        * sizeof(float);  // ~138.4 KB
    cudaFuncSetAttribute(k_mlp, cudaFuncAttributeMaxDynamicSharedMemorySize, (int)smem);

    k_init<<<1, 32>>>();
    k_prep<<<NROWS / 8, 256>>>(x, nx, ac);
    k_mlp<<<NA * NT, NTHR, smem>>>(W1, b1, W2, b2, W3, b3, W4, b4);
    k_fin<<<1, 64>>>((float*)d_out, out_size);
}

// round 4
// speedup vs baseline: 3.7449x; 2.7709x over previous
#include <cuda_runtime.h>
#include <cuda_bf16.h>
#include <stdint.h>

#define NROWS 65536
#define XD    362
#define NA    3
#define TILE  128
#define NT    (NROWS / TILE)   // 512
#define NTHR  256

// pitches (bf16 elements) chosen for conflict-free ldmatrix
#define P_H1  120   // H1: 128 x 112(K-pad) bf16
#define P_W2  120   // W2t half: 200 x 112 bf16
#define P_H2  408   // H2: 128 x 400 bf16
#define P_W3  216   // W3t K-half: 104 x (192|208) bf16

// ---------------- device scratch ----------------
__device__ float  g_att  [(size_t)NA * NROWS * 6];
__device__ float  g_delta[(size_t)NA * NROWS * 6];
__device__ int    g_cnt[NA];
__device__ double g_acc;
__device__ uint4  g_w2t_u4[(size_t)NA * 400 * 14];  // [a][n<400][k<112] bf16
__device__ uint4  g_w3t_u4[(size_t)NA * 104 * 50];  // [a][n<104][k<400] bf16

// ---------------- helpers ----------------
__device__ __forceinline__ uint32_t smem_u32(const void* p) {
    uint32_t a;
    asm("{ .reg .u64 t; cvta.to.shared.u64 t, %1; cvt.u32.u64 %0, t; }" : "=r"(a) : "l"(p));
    return a;
}
#define CVT_BF16X2(res, lo, hi) \
    asm("cvt.rn.bf16x2.f32 %0, %1, %2;" : "=r"(res) : "f"(hi), "f"(lo))

__device__ __forceinline__ void ldmA(uint32_t* a, uint32_t addr) {
    asm volatile("ldmatrix.sync.aligned.m8n8.x4.shared.b16 {%0,%1,%2,%3}, [%4];"
        : "=r"(a[0]), "=r"(a[1]), "=r"(a[2]), "=r"(a[3]) : "r"(addr));
}
__device__ __forceinline__ void ldmB(uint32_t& b0, uint32_t& b1, uint32_t addr) {
    asm volatile("ldmatrix.sync.aligned.m8n8.x2.shared.b16 {%0,%1}, [%2];"
        : "=r"(b0), "=r"(b1) : "r"(addr));
}
__device__ __forceinline__ void mma16816(float* c, const uint32_t* a, uint32_t b0, uint32_t b1) {
    asm volatile("mma.sync.aligned.m16n8k16.row.col.f32.bf16.bf16.f32 "
        "{%0,%1,%2,%3}, {%4,%5,%6,%7}, {%8,%9}, {%0,%1,%2,%3};"
        : "+f"(c[0]), "+f"(c[1]), "+f"(c[2]), "+f"(c[3])
        : "r"(a[0]), "r"(a[1]), "r"(a[2]), "r"(a[3]), "r"(b0), "r"(b1));
}
// ldmatrix.x4 source address for a 16x16 bf16 tile at (m0,k0), row pitch P (elems)
__device__ __forceinline__ uint32_t addrA(uint32_t base, int lane, int m0, int k0, int P) {
    int j = lane >> 3;
    int row = m0 + ((j & 1) << 3) + (lane & 7);
    int col = k0 + ((j >> 1) << 3);
    return base + (uint32_t)(row * P + col) * 2u;
}
// ldmatrix.x2 source address for an 8n x 16k tile of Wt at (n0,k0), pitch P
__device__ __forceinline__ uint32_t addrB(uint32_t base, int lane, int n0, int k0, int P) {
    int l = lane & 15;
    int row = n0 + (l & 7);
    int col = k0 + ((l >> 3) << 3);
    return base + (uint32_t)(row * P + col) * 2u;
}

// ---------------- small kernels ----------------
__global__ void k_init() {
    int t = threadIdx.x;
    if (t < NA) g_cnt[t] = 0;
    if (t == 0) g_acc = 0.0;
}

// transpose + bf16 + zero-pad weights
__global__ void k_wprep(const float* __restrict__ W2, const float* __restrict__ W3) {
    int i = blockIdx.x * blockDim.x + threadIdx.x;
    int stride = gridDim.x * blockDim.x;
    __nv_bfloat16* w2t = (__nv_bfloat16*)g_w2t_u4;
    __nv_bfloat16* w3t = (__nv_bfloat16*)g_w3t_u4;
    for (int t = i; t < NA * 400 * 112; t += stride) {
        int k = t % 112, n = (t / 112) % 400, a = t / (112 * 400);
        float v = (k < 100) ? W2[(size_t)a * 40000 + k * 400 + n] : 0.f;
        w2t[t] = __float2bfloat16(v);
    }
    for (int t = i; t < NA * 104 * 400; t += stride) {
        int k = t % 400, n = (t / 400) % 104, a = t / (400 * 104);
        float v = (n < 100) ? W3[(size_t)a * 40000 + k * 100 + n] : 0.f;
        w3t[t] = __float2bfloat16(v);
    }
}

// One warp per row: sentinel search, gather 6 cells, bucket-scatter by action.
__global__ void k_prep(const float* __restrict__ x, const float* __restrict__ nx,
                       const int* __restrict__ act) {
    int w    = (blockIdx.x * blockDim.x + threadIdx.x) >> 5;
    int lane = threadIdx.x & 31;
    if (w >= NROWS) return;
    const float* xr = x + (size_t)w * XD;

    int found = 0x7fffffff;
    for (int base = 0; base < XD; base += 32) {
        int i = base + lane;
        float v = (i < XD) ? __ldg(xr + i) : 0.f;
        bool hit = (v == 10.0f);
        if (hit) found = i;
        if (__ballot_sync(0xffffffffu, hit)) break;
    }
    #pragma unroll
    for (int off = 16; off; off >>= 1)
        found = min(found, __shfl_xor_sync(0xffffffffu, found, off));
    int p = found;
    if (p < 19 || p >= XD - 19) p = 20;

    int a = act[w];
    int slot = 0;
    if (lane == 0) slot = atomicAdd(&g_cnt[a], 1);
    slot = __shfl_sync(0xffffffffu, slot, 0);

    if (lane < 6) {
        int idx = 0;
        if      (lane == 1) idx = p;
        else if (lane == 2) idx = p - 19;
        else if (lane == 3) idx = p + 19;
        else if (lane == 4) idx = p - 1;
        else if (lane == 5) idx = p + 1;
        float av = xr[idx];
        float nv = nx[(size_t)w * XD + idx];
        size_t o = ((size_t)a * NROWS + (size_t)slot) * 6 + lane;
        g_att[o]   = av;
        g_delta[o] = nv - av;
    }
}

// ---------------- smem layout (bytes) ----------------
#define O_H1   0u                           // 128*120*2 = 30720
#define O_WBUF 30720u                       // max(200*120*2, 104*216*2) = 48000
#define O_H2   78720u                       // 128*408*2 = 104448 (later H3 f32 128x104)
#define O_SX   183168u                      // 128*6*4
#define O_SD   186240u
#define O_W1   189312u                      // 6*100*4
#define O_B1   191712u
#define O_B2   192112u                      // 400*4
#define O_B3   193712u
#define O_W4   194112u                      // 100*6*4
#define O_B4   196512u                      // 8*4
#define O_RED  196544u                      // 8*4
#define SMEM_REQ 196576u

__device__ __forceinline__ void stage_w2(char* sb, int a, int half, int tid) {
    const uint4* src = g_w2t_u4 + ((size_t)a * 400 + half * 200) * 14;
    for (int i = tid; i < 200 * 14; i += NTHR) {
        int n = i / 14, q = i - n * 14;
        *(uint4*)(sb + O_WBUF + n * (P_W2 * 2) + q * 16) = src[i];
    }
}
__device__ __forceinline__ void stage_w3(char* sb, int a, int kh, int tid) {
    const uint4* src = g_w3t_u4 + (size_t)a * 104 * 50;
    const int nq = kh ? 26 : 24;
    const int q0 = kh ? 24 : 0;
    for (int i = tid; i < 104 * nq; i += NTHR) {
        int n = i / nq, q = i - n * nq;
        *(uint4*)(sb + O_WBUF + n * (P_W3 * 2) + q * 16) = src[n * 50 + q0 + q];
    }
}

// ---------------- fused MLP tile kernel (HMMA) ----------------
__global__ __launch_bounds__(NTHR, 1)
void k_mlp(const float* __restrict__ W1, const float* __restrict__ b1,
           const float* __restrict__ b2, const float* __restrict__ b3,
           const float* __restrict__ W4, const float* __restrict__ b4) {
    extern __shared__ char sb[];
    const uint32_t sb32 = smem_u32(sb);

    const int a    = blockIdx.x / NT;
    const int t    = blockIdx.x % NT;
    const int cnt  = g_cnt[a];
    const int row0 = t * TILE;
    if (row0 >= cnt) return;
    const int nrows = min(TILE, cnt - row0);
    const int tid   = threadIdx.x;
    const int wid   = tid >> 5;
    const int lane  = tid & 31;
    const int m0    = wid * 16;

    float* sX  = (float*)(sb + O_SX);
    float* sD  = (float*)(sb + O_SD);
    float* sW1 = (float*)(sb + O_W1);
    float* sB1 = (float*)(sb + O_B1);
    float* sB2 = (float*)(sb + O_B2);
    float* sB3 = (float*)(sb + O_B3);
    float* sW4 = (float*)(sb + O_W4);
    float* sB4 = (float*)(sb + O_B4);
    float* sRed = (float*)(sb + O_RED);

    {   // stage inputs + small weights
        const float* gA = g_att   + ((size_t)a * NROWS + row0) * 6;
        const float* gD = g_delta + ((size_t)a * NROWS + row0) * 6;
        for (int i = tid; i < TILE * 6; i += NTHR) { sX[i] = gA[i]; sD[i] = gD[i]; }
        for (int i = tid; i < 600; i += NTHR) sW1[i] = W1[a * 600 + i];
        for (int i = tid; i < 600; i += NTHR) sW4[i] = W4[a * 600 + i];
        for (int i = tid; i < 400; i += NTHR) sB2[i] = b2[a * 400 + i];
        if (tid < 100) sB1[tid] = b1[a * 100 + tid];
        if (tid < 100) sB3[tid] = b3[a * 100 + tid];
        if (tid < 8)   sB4[tid] = (tid < 6) ? b4[a * 6 + tid] : 0.f;
    }
    __syncthreads();

    // ---- layer 1 (fp32) -> H1 bf16 [128][P_H1], zero-pad K 100..119 ----
    {
        const int r = tid & 127;
        const int h = tid >> 7;
        const float* xr = sX + r * 6;
        __nv_bfloat16* H1 = (__nv_bfloat16*)(sb + O_H1);
        #pragma unroll
        for (int c = 0; c < 50; c += 2) {
            int j = h * 50 + c;
            float s0 = sB1[j], s1 = sB1[j + 1];
            #pragma unroll
            for (int k = 0; k < 6; k++) {
                s0 = fmaf(xr[k], sW1[k * 100 + j], s0);
                s1 = fmaf(xr[k], sW1[k * 100 + j + 1], s1);
            }
            uint32_t pk; CVT_BF16X2(pk, fmaxf(s0, 0.f), fmaxf(s1, 0.f));
            *(uint32_t*)((char*)H1 + (r * P_H1 + j) * 2) = pk;
        }
        if (h == 1) {
            #pragma unroll
            for (int j = 100; j < 120; j += 2)
                *(uint32_t*)((char*)H1 + (r * P_H1 + j) * 2) = 0u;
        }
    }
    __syncthreads();

    // cache layer-2 A fragments (H1, 7 K-steps)
    uint32_t a2f[7][4];
    #pragma unroll
    for (int ks = 0; ks < 7; ks++)
        ldmA(a2f[ks], addrA(sb32 + O_H1, lane, m0, ks * 16, P_H1));

    // ---- layer 2: H2[128][400] = relu(H1 @ W2 + b2), W staged in 2 N-halves ----
    for (int half = 0; half < 2; half++) {
        stage_w2(sb, a, half, tid);
        __syncthreads();
        const uint32_t wb = sb32 + O_WBUF;
        for (int nt = 0; nt < 25; nt++) {
            float c[4] = {0.f, 0.f, 0.f, 0.f};
            #pragma unroll
            for (int ks = 0; ks < 7; ks++) {
                uint32_t b0, b1v;
                ldmB(b0, b1v, addrB(wb, lane, nt * 8, ks * 16, P_W2));
                mma16816(c, a2f[ks], b0, b1v);
            }
            int cg = half * 200 + nt * 8 + 2 * (lane & 3);
            int r0 = m0 + (lane >> 2);
            float f0 = fmaxf(c[0] + sB2[cg],     0.f);
            float f1 = fmaxf(c[1] + sB2[cg + 1], 0.f);
            float f2 = fmaxf(c[2] + sB2[cg],     0.f);
            float f3 = fmaxf(c[3] + sB2[cg + 1], 0.f);
            uint32_t p0, p1;
            CVT_BF16X2(p0, f0, f1);
            CVT_BF16X2(p1, f2, f3);
            *(uint32_t*)(sb + O_H2 + (r0 * P_H2 + cg) * 2)       = p0;
            *(uint32_t*)(sb + O_H2 + ((r0 + 8) * P_H2 + cg) * 2) = p1;
        }
        __syncthreads();
    }

    // ---- layer 3: H3[128][100] = relu(H2 @ W3 + b3), K=400 in 2 staged halves ----
    float acc[13][4];
    #pragma unroll
    for (int nt = 0; nt < 13; nt++)
        #pragma unroll
        for (int j = 0; j < 4; j++) acc[nt][j] = 0.f;

    for (int kh = 0; kh < 2; kh++) {
        stage_w3(sb, a, kh, tid);
        __syncthreads();
        const uint32_t wb = sb32 + O_WBUF;
        const int nks = kh ? 13 : 12;
        for (int ks = 0; ks < nks; ks++) {
            uint32_t af[4];
            ldmA(af, addrA(sb32 + O_H2, lane, m0, kh * 192 + ks * 16, P_H2));
            #pragma unroll
            for (int nt = 0; nt < 13; nt++) {
                uint32_t b0, b1v;
                ldmB(b0, b1v, addrB(wb, lane, nt * 8, ks * 16, P_W3));
                mma16816(acc[nt], af, b0, b1v);
            }
        }
        __syncthreads();   // guards WBUF restage / H2->H3 overwrite
    }

    // epilogue: +b3, relu -> H3 fp32 [128][104] over H2 region
    float* H3 = (float*)(sb + O_H2);
    {
        const int r0 = m0 + (lane >> 2);
        #pragma unroll
        for (int nt = 0; nt < 13; nt++) {
            int c = nt * 8 + 2 * (lane & 3);
            if (c < 100) {
                float2 v0 = make_float2(fmaxf(acc[nt][0] + sB3[c], 0.f),
                                        fmaxf(acc[nt][1] + sB3[c + 1], 0.f));
                float2 v1 = make_float2(fmaxf(acc[nt][2] + sB3[c], 0.f),
                                        fmaxf(acc[nt][3] + sB3[c + 1], 0.f));
                *(float2*)(H3 + r0 * 104 + c)       = v0;
                *(float2*)(H3 + (r0 + 8) * 104 + c) = v1;
            }
        }
    }
    __syncthreads();

    // ---- layer 4 + squared error ----
    float local = 0.f;
    for (int o = tid; o < TILE * 6; o += NTHR) {
        int r = o & 127, c = o >> 7;
        float s = sB4[c];
        #pragma unroll 4
        for (int k = 0; k < 100; k++) s = fmaf(H3[r * 104 + k], sW4[k * 6 + c], s);
        if (r < nrows) { float d = s - sD[r * 6 + c]; local += d * d; }
    }
    #pragma unroll
    for (int off = 16; off; off >>= 1) local += __shfl_xor_sync(0xffffffffu, local, off);
    if (lane == 0) sRed[wid] = local;
    __syncthreads();
    if (tid == 0) {
        float s = 0.f;
        #pragma unroll
        for (int i = 0; i < 8; i++) s += sRed[i];
        atomicAdd(&g_acc, (double)s);
    }
}

__global__ void k_fin(float* out, int n) {
    float v = (float)(g_acc / ((double)NROWS * 6.0));
    for (int i = threadIdx.x; i < n; i += blockDim.x) out[i] = v;
}

extern "C" void kernel_launch(void* const* d_in, const int* in_sizes, int n_in,
                              void* d_out, int out_size) {
    const float* x  = (const float*)d_in[0];
    const float* nx = (const float*)d_in[1];
    const int*   ac = (const int*)d_in[2];
    const float* W1 = (const float*)d_in[3];
    const float* b1 = (const float*)d_in[4];
    const float* W2 = (const float*)d_in[5];
    const float* b2 = (const float*)d_in[6];
    const float* W3 = (const float*)d_in[7];
    const float* b3 = (const float*)d_in[8];
    const float* W4 = (const float*)d_in[9];
    const float* b4 = (const float*)d_in[10];

    cudaFuncSetAttribute(k_mlp, cudaFuncAttributeMaxDynamicSharedMemorySize, (int)SMEM_REQ);

    k_init<<<1, 32>>>();
    k_wprep<<<128, 256>>>(W2, W3);
    k_prep<<<NROWS / 8, 256>>>(x, nx, ac);
    k_mlp<<<NA * NT, NTHR, SMEM_REQ>>>(W1, b1, b2, b3, W4, b4);
    k_fin<<<1, 64>>>((float*)d_out, out_size);
}

// round 5
// speedup vs baseline: 4.8207x; 1.2873x over previous
#include <cuda_runtime.h>
#include <cuda_bf16.h>
#include <stdint.h>

#define NROWS 65536
#define XD    362
#define NA    3
#define TILE  256
#define NT    (NROWS / TILE)   // 256
#define NTHR  512

#define P_H1  120   // bf16 pitch, conflict-free ldmatrix
#define P_W2  120
#define P_W3  216
#define P_H3  105   // fp32 pitch, conflict-free layer-4 LDS

// ---------------- device scratch ----------------
__device__ float  g_att  [(size_t)NA * NROWS * 6];
__device__ float  g_delta[(size_t)NA * NROWS * 6];
__device__ int    g_cnt[NA];
__device__ double g_acc;
__device__ uint4  g_w2t_u4[(size_t)NA * 400 * 14];  // [a][n<400][k<112] bf16
__device__ uint4  g_w3t_u4[(size_t)NA * 104 * 50];  // [a][n<104][k<400] bf16

// ---------------- helpers ----------------
__device__ __forceinline__ uint32_t smem_u32(const void* p) {
    uint32_t a;
    asm("{ .reg .u64 t; cvta.to.shared.u64 t, %1; cvt.u32.u64 %0, t; }" : "=r"(a) : "l"(p));
    return a;
}
#define CVT_BF16X2(res, lo, hi) \
    asm("cvt.rn.bf16x2.f32 %0, %1, %2;" : "=r"(res) : "f"(hi), "f"(lo))

__device__ __forceinline__ void ldmA(uint32_t* a, uint32_t addr) {
    asm volatile("ldmatrix.sync.aligned.m8n8.x4.shared.b16 {%0,%1,%2,%3}, [%4];"
        : "=r"(a[0]), "=r"(a[1]), "=r"(a[2]), "=r"(a[3]) : "r"(addr));
}
__device__ __forceinline__ void ldmB(uint32_t& b0, uint32_t& b1, uint32_t addr) {
    asm volatile("ldmatrix.sync.aligned.m8n8.x2.shared.b16 {%0,%1}, [%2];"
        : "=r"(b0), "=r"(b1) : "r"(addr));
}
__device__ __forceinline__ void mma16816(float* c, const uint32_t* a, uint32_t b0, uint32_t b1) {
    asm volatile("mma.sync.aligned.m16n8k16.row.col.f32.bf16.bf16.f32 "
        "{%0,%1,%2,%3}, {%4,%5,%6,%7}, {%8,%9}, {%0,%1,%2,%3};"
        : "+f"(c[0]), "+f"(c[1]), "+f"(c[2]), "+f"(c[3])
        : "r"(a[0]), "r"(a[1]), "r"(a[2]), "r"(a[3]), "r"(b0), "r"(b1));
}
__device__ __forceinline__ uint32_t addrA(uint32_t base, int lane, int m0, int k0, int P) {
    int j = lane >> 3;
    int row = m0 + ((j & 1) << 3) + (lane & 7);
    int col = k0 + ((j >> 1) << 3);
    return base + (uint32_t)(row * P + col) * 2u;
}
__device__ __forceinline__ uint32_t addrB(uint32_t base, int lane, int n0, int k0, int P) {
    int l = lane & 15;
    int row = n0 + (l & 7);
    int col = k0 + ((l >> 3) << 3);
    return base + (uint32_t)(row * P + col) * 2u;
}

// ---------------- prep kernels ----------------
// transpose + bf16 + zero-pad weights; block 0 also resets counters.
__global__ void k_wprep(const float* __restrict__ W2, const float* __restrict__ W3) {
    if (blockIdx.x == 0 && threadIdx.x < 4) {
        if (threadIdx.x < NA) g_cnt[threadIdx.x] = 0;
        if (threadIdx.x == 3) g_acc = 0.0;
    }
    int i = blockIdx.x * blockDim.x + threadIdx.x;
    int stride = gridDim.x * blockDim.x;
    __nv_bfloat16* w2t = (__nv_bfloat16*)g_w2t_u4;
    __nv_bfloat16* w3t = (__nv_bfloat16*)g_w3t_u4;
    for (int t = i; t < NA * 400 * 112; t += stride) {
        int k = t % 112, n = (t / 112) % 400, a = t / (112 * 400);
        float v = (k < 100) ? W2[(size_t)a * 40000 + k * 400 + n] : 0.f;
        w2t[t] = __float2bfloat16(v);
    }
    for (int t = i; t < NA * 104 * 400; t += stride) {
        int k = t % 400, n = (t / 400) % 104, a = t / (400 * 104);
        float v = (n < 100) ? W3[(size_t)a * 40000 + k * 100 + n] : 0.f;
        w3t[t] = __float2bfloat16(v);
    }
}

// One warp per row: sentinel search (float2, early exit), gather, bucket-scatter.
__global__ void k_prep(const float* __restrict__ x, const float* __restrict__ nx,
                       const int* __restrict__ act) {
    int w    = (blockIdx.x * blockDim.x + threadIdx.x) >> 5;
    int lane = threadIdx.x & 31;
    if (w >= NROWS) return;
    const float* xr = x + (size_t)w * XD;

    int found = 0x7fffffff;
    for (int base = 0; base < XD; base += 64) {
        int i2 = base + 2 * lane;
        float2 v = make_float2(0.f, 0.f);
        if (i2 + 1 < XD) v = *(const float2*)(xr + i2);
        int f = 0x7fffffff;
        if (v.y == 10.0f) f = i2 + 1;
        if (v.x == 10.0f) f = i2;
        if (f < found) found = f;
        if (__ballot_sync(0xffffffffu, f != 0x7fffffff)) break;
    }
    #pragma unroll
    for (int off = 16; off; off >>= 1)
        found = min(found, __shfl_xor_sync(0xffffffffu, found, off));
    int p = found;
    if (p < 19 || p >= XD - 19) p = 20;

    int a = act[w];
    int slot = 0;
    if (lane == 0) slot = atomicAdd(&g_cnt[a], 1);
    slot = __shfl_sync(0xffffffffu, slot, 0);

    if (lane < 6) {
        int idx = 0;
        if      (lane == 1) idx = p;
        else if (lane == 2) idx = p - 19;
        else if (lane == 3) idx = p + 19;
        else if (lane == 4) idx = p - 1;
        else if (lane == 5) idx = p + 1;
        float av = xr[idx];
        float nv = nx[(size_t)w * XD + idx];
        size_t o = ((size_t)a * NROWS + (size_t)slot) * 6 + lane;
        g_att[o]   = av;
        g_delta[o] = nv - av;
    }
}

// ---------------- smem layout (bytes) ----------------
#define O_H1   0u         // 256*120*2 = 61440
#define O_W2B  61440u     // 208*120*2 = 49920 (slab buffer)
#define O_W3B  111360u    // 104*216*2 = 44928 (slab buffer)
#define O_SX   156288u    // 256*6*4
#define O_SD   162432u
#define O_W1   168576u    // 600*4
#define O_B1   170976u
#define O_B2   171376u    // 400*4
#define O_B3   172976u
#define O_W4   173376u    // 600*4
#define O_B4   175776u    // 8*4
#define O_RED  175808u    // 16*4
#define SMEM_REQ 175872u
// H3 fp32 [256][105] = 107520 B overlays H1+W2B after both dead.

__device__ __forceinline__ void stage_w2(char* sb, int a, int c0, int nrow, int tid) {
    const uint4* src = g_w2t_u4 + ((size_t)a * 400 + c0) * 14;
    for (int i = tid; i < nrow * 14; i += NTHR) {
        int n = i / 14, q = i - n * 14;
        *(uint4*)(sb + O_W2B + n * (P_W2 * 2) + q * 16) = src[i];
    }
}
__device__ __forceinline__ void stage_w3(char* sb, int a, int k0, int nk, int tid) {
    const uint4* src = g_w3t_u4 + (size_t)a * 104 * 50 + (k0 >> 3);
    const int nq = nk >> 3;
    for (int i = tid; i < 104 * nq; i += NTHR) {
        int n = i / nq, q = i - n * nq;
        *(uint4*)(sb + O_W3B + n * (P_W3 * 2) + q * 16) = src[n * 50 + q];
    }
}

// ---------------- fused MLP tile kernel ----------------
__global__ __launch_bounds__(NTHR, 1)
void k_mlp(const float* __restrict__ W1, const float* __restrict__ b1,
           const float* __restrict__ b2, const float* __restrict__ b3,
           const float* __restrict__ W4, const float* __restrict__ b4) {
    extern __shared__ char sb[];
    const uint32_t sb32 = smem_u32(sb);

    const int a    = blockIdx.x / NT;
    const int t    = blockIdx.x % NT;
    const int cnt  = g_cnt[a];
    const int row0 = t * TILE;
    if (row0 >= cnt) return;
    const int nrows = min(TILE, cnt - row0);
    const int tid   = threadIdx.x;
    const int wid   = tid >> 5;
    const int lane  = tid & 31;
    const int m0    = wid * 16;

    float* sX  = (float*)(sb + O_SX);
    float* sD  = (float*)(sb + O_SD);
    float* sW1 = (float*)(sb + O_W1);
    float* sB1 = (float*)(sb + O_B1);
    float* sB2 = (float*)(sb + O_B2);
    float* sB3 = (float*)(sb + O_B3);
    float* sW4 = (float*)(sb + O_W4);
    float* sB4 = (float*)(sb + O_B4);
    float* sRed = (float*)(sb + O_RED);

    {   // stage inputs + small weights
        const float* gA = g_att   + ((size_t)a * NROWS + row0) * 6;
        const float* gD = g_delta + ((size_t)a * NROWS + row0) * 6;
        for (int i = tid; i < TILE * 6; i += NTHR) { sX[i] = gA[i]; sD[i] = gD[i]; }
        for (int i = tid; i < 600; i += NTHR) sW1[i] = W1[a * 600 + i];
        for (int i = tid; i < 600; i += NTHR) sW4[i] = W4[a * 600 + i];
        for (int i = tid; i < 400; i += NTHR) sB2[i] = b2[a * 400 + i];
        if (tid < 100) sB1[tid] = b1[a * 100 + tid];
        if (tid < 100) sB3[tid] = b3[a * 100 + tid];
        if (tid < 8)   sB4[tid] = (tid < 6) ? b4[a * 6 + tid] : 0.f;
    }
    __syncthreads();

    // ---- layer 1 (fp32) -> H1 bf16 [256][120], zero-pad k 100..119 ----
    {
        const int r = tid & 255;
        const int h = tid >> 8;
        const float* xr = sX + r * 6;
        #pragma unroll
        for (int c = 0; c < 50; c += 2) {
            int j = h * 50 + c;
            float s0 = sB1[j], s1 = sB1[j + 1];
            #pragma unroll
            for (int k = 0; k < 6; k++) {
                s0 = fmaf(xr[k], sW1[k * 100 + j], s0);
                s1 = fmaf(xr[k], sW1[k * 100 + j + 1], s1);
            }
            uint32_t pk; CVT_BF16X2(pk, fmaxf(s0, 0.f), fmaxf(s1, 0.f));
            *(uint32_t*)(sb + O_H1 + (r * P_H1 + j) * 2) = pk;
        }
        if (h == 1) {
            #pragma unroll
            for (int j = 100; j < 120; j += 2)
                *(uint32_t*)(sb + O_H1 + (r * P_H1 + j) * 2) = 0u;
        }
    }
    __syncthreads();

    // cache layer-2 A fragments (persist across both halves)
    uint32_t a2f[7][4];
    #pragma unroll
    for (int ks = 0; ks < 7; ks++)
        ldmA(a2f[ks], addrA(sb32 + O_H1, lane, m0, ks * 16, P_H1));

    // layer-3 accumulators persist across both halves
    float acc[13][4];
    #pragma unroll
    for (int nt = 0; nt < 13; nt++)
        #pragma unroll
        for (int j = 0; j < 4; j++) acc[nt][j] = 0.f;

    const uint32_t w2b = sb32 + O_W2B;
    const uint32_t w3b = sb32 + O_W3B;

    // ---- fused layers 2+3 over two K/N halves; H2 stays in registers ----
    #pragma unroll
    for (int half = 0; half < 2; half++) {
        const int c0   = half ? 192 : 0;
        const int kb_s = half ? 12 : 0;
        const int kb_e = half ? 25 : 12;
        stage_w2(sb, a, c0, half ? 208 : 192, tid);
        stage_w3(sb, a, c0, half ? 208 : 192, tid);
        __syncthreads();

        for (int kb = kb_s; kb < kb_e; kb++) {
            // layer-2: two adjacent 8-col tiles (cols kb*16 .. kb*16+15)
            float c0v[4] = {0.f, 0.f, 0.f, 0.f};
            float c1v[4] = {0.f, 0.f, 0.f, 0.f};
            const int nloc = kb * 16 - c0;
            #pragma unroll
            for (int ks = 0; ks < 7; ks++) {
                uint32_t b0, b1v, b2v, b3v;
                ldmB(b0, b1v, addrB(w2b, lane, nloc,     ks * 16, P_W2));
                ldmB(b2v, b3v, addrB(w2b, lane, nloc + 8, ks * 16, P_W2));
                mma16816(c0v, a2f[ks], b0, b1v);
                mma16816(c1v, a2f[ks], b2v, b3v);
            }
            // epilogue -> layer-3 A fragment (C frag == A frag halves)
            const int cA = kb * 16 + 2 * (lane & 3);
            uint32_t afr[4];
            {
                float g0 = sB2[cA],     g1 = sB2[cA + 1];
                float g2 = sB2[cA + 8], g3 = sB2[cA + 9];
                CVT_BF16X2(afr[0], fmaxf(c0v[0] + g0, 0.f), fmaxf(c0v[1] + g1, 0.f));
                CVT_BF16X2(afr[1], fmaxf(c0v[2] + g0, 0.f), fmaxf(c0v[3] + g1, 0.f));
                CVT_BF16X2(afr[2], fmaxf(c1v[0] + g2, 0.f), fmaxf(c1v[1] + g3, 0.f));
                CVT_BF16X2(afr[3], fmaxf(c1v[2] + g2, 0.f), fmaxf(c1v[3] + g3, 0.f));
            }
            // layer-3: 13 independent accumulations, k-block = kb
            const int kloc = kb * 16 - c0;
            #pragma unroll
            for (int nt = 0; nt < 13; nt++) {
                uint32_t b0, b1v;
                ldmB(b0, b1v, addrB(w3b, lane, nt * 8, kloc, P_W3));
                mma16816(acc[nt], afr, b0, b1v);
            }
        }
        __syncthreads();
    }

    // ---- layer-3 epilogue: +b3, relu -> H3 fp32 [256][105] (overlays H1/W2B) ----
    float* H3 = (float*)(sb + O_H1);
    {
        const int r0 = m0 + (lane >> 2);
        #pragma unroll
        for (int nt = 0; nt < 13; nt++) {
            int c = nt * 8 + 2 * (lane & 3);
            if (c < 100) {
                H3[r0 * P_H3 + c]           = fmaxf(acc[nt][0] + sB3[c],     0.f);
                H3[r0 * P_H3 + c + 1]       = fmaxf(acc[nt][1] + sB3[c + 1], 0.f);
                H3[(r0 + 8) * P_H3 + c]     = fmaxf(acc[nt][2] + sB3[c],     0.f);
                H3[(r0 + 8) * P_H3 + c + 1] = fmaxf(acc[nt][3] + sB3[c + 1], 0.f);
            }
        }
    }
    __syncthreads();

    // ---- layer 4 + squared error ----
    float local = 0.f;
    #pragma unroll
    for (int j = 0; j < 3; j++) {
        int o = tid + j * NTHR;
        int r = o & 255, c = o >> 8;
        float s = sB4[c];
        #pragma unroll 4
        for (int k = 0; k < 100; k++) s = fmaf(H3[r * P_H3 + k], sW4[k * 6 + c], s);
        if (r < nrows) { float d = s - sD[r * 6 + c]; local += d * d; }
    }
    #pragma unroll
    for (int off = 16; off; off >>= 1) local += __shfl_xor_sync(0xffffffffu, local, off);
    if (lane == 0) sRed[wid] = local;
    __syncthreads();
    if (tid == 0) {
        float s = 0.f;
        #pragma unroll
        for (int i = 0; i < 16; i++) s += sRed[i];
        atomicAdd(&g_acc, (double)s);
    }
}

__global__ void k_fin(float* out, int n) {
    float v = (float)(g_acc / ((double)NROWS * 6.0));
    for (int i = threadIdx.x; i < n; i += blockDim.x) out[i] = v;
}

extern "C" void kernel_launch(void* const* d_in, const int* in_sizes, int n_in,
                              void* d_out, int out_size) {
    const float* x  = (const float*)d_in[0];
    const float* nx = (const float*)d_in[1];
    const int*   ac = (const int*)d_in[2];
    const float* W1 = (const float*)d_in[3];
    const float* b1 = (const float*)d_in[4];
    const float* W2 = (const float*)d_in[5];
    const float* b2 = (const float*)d_in[6];
    const float* W3 = (const float*)d_in[7];
    const float* b3 = (const float*)d_in[8];
    const float* W4 = (const float*)d_in[9];
    const float* b4 = (const float*)d_in[10];

    cudaFuncSetAttribute(k_mlp, cudaFuncAttributeMaxDynamicSharedMemorySize, (int)SMEM_REQ);

    k_wprep<<<128, 256>>>(W2, W3);
    k_prep<<<NROWS / 8, 256>>>(x, nx, ac);
    k_mlp<<<NA * NT, NTHR, SMEM_REQ>>>(W1, b1, b2, b3, W4, b4);
    k_fin<<<1, 64>>>((float*)d_out, out_size);
}

// round 6
// speedup vs baseline: 4.9579x; 1.0285x over previous
#include <cuda_runtime.h>
#include <cuda_bf16.h>
#include <stdint.h>

#define NROWS 65536
#define XD    362
#define NA    3
#define TILE  256
#define NT    (NROWS / TILE)   // 256
#define NTHR  512

#define P_H1  120   // bf16 pitch, conflict-free ldmatrix
#define P_W2  120
#define P_W3  216
#define P_H3  105   // fp32 pitch, conflict-free layer-4 LDS

// ---------------- device scratch (statically zero at load) ----------------
__device__ float  g_att  [(size_t)NA * NROWS * 6];
__device__ float  g_delta[(size_t)NA * NROWS * 6];
__device__ int    g_cnt[NA];          // reset by k_fin each sequence
__device__ double g_acc;              // reset by k_fin each sequence
__device__ uint4  g_w2t_u4[(size_t)NA * 400 * 14];  // [a][n<400][k<112] bf16
__device__ uint4  g_w3t_u4[(size_t)NA * 104 * 50];  // [a][n<104][k<400] bf16

// ---------------- helpers ----------------
__device__ __forceinline__ uint32_t smem_u32(const void* p) {
    uint32_t a;
    asm("{ .reg .u64 t; cvta.to.shared.u64 t, %1; cvt.u32.u64 %0, t; }" : "=r"(a) : "l"(p));
    return a;
}
#define CVT_BF16X2(res, lo, hi) \
    asm("cvt.rn.bf16x2.f32 %0, %1, %2;" : "=r"(res) : "f"(hi), "f"(lo))

__device__ __forceinline__ void ldmA(uint32_t* a, uint32_t addr) {
    asm volatile("ldmatrix.sync.aligned.m8n8.x4.shared.b16 {%0,%1,%2,%3}, [%4];"
        : "=r"(a[0]), "=r"(a[1]), "=r"(a[2]), "=r"(a[3]) : "r"(addr));
}
__device__ __forceinline__ void ldmB2(uint32_t& b0, uint32_t& b1, uint32_t addr) {
    asm volatile("ldmatrix.sync.aligned.m8n8.x2.shared.b16 {%0,%1}, [%2];"
        : "=r"(b0), "=r"(b1) : "r"(addr));
}
__device__ __forceinline__ void ldmB4(uint32_t* b, uint32_t addr) {
    asm volatile("ldmatrix.sync.aligned.m8n8.x4.shared.b16 {%0,%1,%2,%3}, [%4];"
        : "=r"(b[0]), "=r"(b[1]), "=r"(b[2]), "=r"(b[3]) : "r"(addr));
}
__device__ __forceinline__ void mma16816(float* c, const uint32_t* a, uint32_t b0, uint32_t b1) {
    asm volatile("mma.sync.aligned.m16n8k16.row.col.f32.bf16.bf16.f32 "
        "{%0,%1,%2,%3}, {%4,%5,%6,%7}, {%8,%9}, {%0,%1,%2,%3};"
        : "+f"(c[0]), "+f"(c[1]), "+f"(c[2]), "+f"(c[3])
        : "r"(a[0]), "r"(a[1]), "r"(a[2]), "r"(a[3]), "r"(b0), "r"(b1));
}
__device__ __forceinline__ uint32_t addrA(uint32_t base, int lane, int m0, int k0, int P) {
    int j = lane >> 3;
    int row = m0 + ((j & 1) << 3) + (lane & 7);
    int col = k0 + ((j >> 1) << 3);
    return base + (uint32_t)(row * P + col) * 2u;
}
// x2 B: lanes 0-15 → (n0..n0+7) x (k0 | k0+8)
__device__ __forceinline__ uint32_t addrB2(uint32_t base, int lane, int n0, int k0, int P) {
    int l = lane & 15;
    int row = n0 + (l & 7);
    int col = k0 + ((l >> 3) << 3);
    return base + (uint32_t)(row * P + col) * 2u;
}
// x4 B: b[0..1] = frag(n0), b[2..3] = frag(n0+8)
__device__ __forceinline__ uint32_t addrB4(uint32_t base, int lane, int n0, int k0, int P) {
    int row = n0 + ((lane >> 4) << 3) + (lane & 7);
    int col = k0 + (((lane >> 3) & 1) << 3);
    return base + (uint32_t)(row * P + col) * 2u;
}

// ---------------- combined prep kernel ----------------
// blocks [0, NROWS/8): warp-per-row sentinel+gather+bucket-scatter
// blocks [NROWS/8, +32): weight transpose/bf16/pad
#define PREP_BLKS (NROWS / 8)
#define WPREP_BLKS 32

__global__ void k_prep(const float* __restrict__ x, const float* __restrict__ nx,
                       const int* __restrict__ act,
                       const float* __restrict__ W2, const float* __restrict__ W3) {
    if (blockIdx.x >= PREP_BLKS) {
        int i = (blockIdx.x - PREP_BLKS) * blockDim.x + threadIdx.x;
        int stride = WPREP_BLKS * blockDim.x;
        __nv_bfloat16* w2t = (__nv_bfloat16*)g_w2t_u4;
        __nv_bfloat16* w3t = (__nv_bfloat16*)g_w3t_u4;
        for (int t = i; t < NA * 400 * 112; t += stride) {
            int k = t % 112, n = (t / 112) % 400, a = t / (112 * 400);
            float v = (k < 100) ? W2[(size_t)a * 40000 + k * 400 + n] : 0.f;
            w2t[t] = __float2bfloat16(v);
        }
        for (int t = i; t < NA * 104 * 400; t += stride) {
            int k = t % 400, n = (t / 400) % 104, a = t / (400 * 104);
            float v = (n < 100) ? W3[(size_t)a * 40000 + k * 100 + n] : 0.f;
            w3t[t] = __float2bfloat16(v);
        }
        return;
    }

    int w    = (blockIdx.x * blockDim.x + threadIdx.x) >> 5;
    int lane = threadIdx.x & 31;
    const float* xr = x + (size_t)w * XD;

    // prefetch idx<256 in 4 independent loads (covers ~73% of sentinels)
    float2 v0 = *(const float2*)(xr + 2 * lane);
    float2 v1 = *(const float2*)(xr + 2 * lane + 64);
    float2 v2 = *(const float2*)(xr + 2 * lane + 128);
    float2 v3 = *(const float2*)(xr + 2 * lane + 192);
    int found = 0x7fffffff;
    if (v3.y == 10.0f) found = 2 * lane + 193;
    if (v3.x == 10.0f) found = 2 * lane + 192;
    if (v2.y == 10.0f) found = 2 * lane + 129;
    if (v2.x == 10.0f) found = 2 * lane + 128;
    if (v1.y == 10.0f) found = 2 * lane + 65;
    if (v1.x == 10.0f) found = 2 * lane + 64;
    if (v0.y == 10.0f) found = 2 * lane + 1;
    if (v0.x == 10.0f) found = 2 * lane;
    if (!__ballot_sync(0xffffffffu, found != 0x7fffffff)) {
        // miss path: remaining 106 elems (idx 256..361)
        int i2 = 256 + 2 * lane;
        float2 v4 = make_float2(0.f, 0.f), v5 = make_float2(0.f, 0.f);
        v4 = *(const float2*)(xr + i2);            // 256..319 all valid
        if (i2 + 65 < XD) v5 = *(const float2*)(xr + i2 + 64);
        if (v5.y == 10.0f) found = i2 + 65;
        if (v5.x == 10.0f) found = i2 + 64;
        if (v4.y == 10.0f) found = i2 + 1;
        if (v4.x == 10.0f) found = i2;
    }
    #pragma unroll
    for (int off = 16; off; off >>= 1)
        found = min(found, __shfl_xor_sync(0xffffffffu, found, off));
    int p = found;
    if (p < 19 || p >= XD - 19) p = 20;

    int a = act[w];
    int slot = 0;
    if (lane == 0) slot = atomicAdd(&g_cnt[a], 1);
    slot = __shfl_sync(0xffffffffu, slot, 0);

    if (lane < 6) {
        int idx = 0;
        if      (lane == 1) idx = p;
        else if (lane == 2) idx = p - 19;
        else if (lane == 3) idx = p + 19;
        else if (lane == 4) idx = p - 1;
        else if (lane == 5) idx = p + 1;
        float av = xr[idx];
        float nv = nx[(size_t)w * XD + idx];
        size_t o = ((size_t)a * NROWS + (size_t)slot) * 6 + lane;
        g_att[o]   = av;
        g_delta[o] = nv - av;
    }
}

// ---------------- smem layout (bytes) ----------------
#define O_H1   0u         // 256*120*2 = 61440
#define O_W2B  61440u     // 208*120*2 = 49920
#define O_W3B  111360u    // 104*216*2 = 44928
#define O_SX   156288u
#define O_SD   162432u
#define O_W1   168576u
#define O_B1   170976u
#define O_B2   171376u
#define O_B3   172976u
#define O_W4   173376u
#define O_B4   175776u
#define O_RED  175808u
#define SMEM_REQ 175872u
// H3 fp32 [256][105] overlays H1+W2B after both are dead.

__device__ __forceinline__ void stage_w2(char* sb, int a, int c0, int nrow, int tid) {
    const uint4* src = g_w2t_u4 + ((size_t)a * 400 + c0) * 14;
    for (int i = tid; i < nrow * 14; i += NTHR) {
        int n = i / 14, q = i - n * 14;
        *(uint4*)(sb + O_W2B + n * (P_W2 * 2) + q * 16) = src[i];
    }
}
__device__ __forceinline__ void stage_w3(char* sb, int a, int k0, int nk, int tid) {
    const uint4* src = g_w3t_u4 + (size_t)a * 104 * 50 + (k0 >> 3);
    const int nq = nk >> 3;
    for (int i = tid; i < 104 * nq; i += NTHR) {
        int n = i / nq, q = i - n * nq;
        *(uint4*)(sb + O_W3B + n * (P_W3 * 2) + q * 16) = src[n * 50 + q];
    }
}

// ---------------- fused MLP tile kernel ----------------
__global__ __launch_bounds__(NTHR, 1)
void k_mlp(const float* __restrict__ W1, const float* __restrict__ b1,
           const float* __restrict__ b2, const float* __restrict__ b3,
           const float* __restrict__ W4, const float* __restrict__ b4) {
    extern __shared__ char sb[];
    const uint32_t sb32 = smem_u32(sb);

    const int a    = blockIdx.x / NT;
    const int t    = blockIdx.x % NT;
    const int cnt  = g_cnt[a];
    const int row0 = t * TILE;
    if (row0 >= cnt) return;
    const int nrows = min(TILE, cnt - row0);
    const int tid   = threadIdx.x;
    const int wid   = tid >> 5;
    const int lane  = tid & 31;
    const int m0    = wid * 16;

    float* sX  = (float*)(sb + O_SX);
    float* sD  = (float*)(sb + O_SD);
    float* sW1 = (float*)(sb + O_W1);
    float* sB1 = (float*)(sb + O_B1);
    float* sB2 = (float*)(sb + O_B2);
    float* sB3 = (float*)(sb + O_B3);
    float* sW4 = (float*)(sb + O_W4);
    float* sB4 = (float*)(sb + O_B4);
    float* sRed = (float*)(sb + O_RED);

    {   // stage inputs + small weights
        const float* gA = g_att   + ((size_t)a * NROWS + row0) * 6;
        const float* gD = g_delta + ((size_t)a * NROWS + row0) * 6;
        for (int i = tid; i < TILE * 6; i += NTHR) { sX[i] = gA[i]; sD[i] = gD[i]; }
        for (int i = tid; i < 600; i += NTHR) sW1[i] = W1[a * 600 + i];
        for (int i = tid; i < 600; i += NTHR) sW4[i] = W4[a * 600 + i];
        for (int i = tid; i < 400; i += NTHR) sB2[i] = b2[a * 400 + i];
        if (tid < 100) sB1[tid] = b1[a * 100 + tid];
        if (tid < 100) sB3[tid] = b3[a * 100 + tid];
        if (tid < 8)   sB4[tid] = (tid < 6) ? b4[a * 6 + tid] : 0.f;
    }
    __syncthreads();

    // ---- layer 1 (fp32) -> H1 bf16 [256][120], zero-pad k 100..119 ----
    {
        const int r = tid & 255;
        const int h = tid >> 8;
        const float* xr = sX + r * 6;
        #pragma unroll
        for (int c = 0; c < 50; c += 2) {
            int j = h * 50 + c;
            float s0 = sB1[j], s1 = sB1[j + 1];
            #pragma unroll
            for (int k = 0; k < 6; k++) {
                s0 = fmaf(xr[k], sW1[k * 100 + j], s0);
                s1 = fmaf(xr[k], sW1[k * 100 + j + 1], s1);
            }
            uint32_t pk; CVT_BF16X2(pk, fmaxf(s0, 0.f), fmaxf(s1, 0.f));
            *(uint32_t*)(sb + O_H1 + (r * P_H1 + j) * 2) = pk;
        }
        if (h == 1) {
            #pragma unroll
            for (int j = 100; j < 120; j += 2)
                *(uint32_t*)(sb + O_H1 + (r * P_H1 + j) * 2) = 0u;
        }
    }
    __syncthreads();

    // cache layer-2 A fragments (persist across both halves)
    uint32_t a2f[7][4];
    #pragma unroll
    for (int ks = 0; ks < 7; ks++)
        ldmA(a2f[ks], addrA(sb32 + O_H1, lane, m0, ks * 16, P_H1));

    // layer-3 accumulators persist across both halves
    float acc[13][4];
    #pragma unroll
    for (int nt = 0; nt < 13; nt++)
        #pragma unroll
        for (int j = 0; j < 4; j++) acc[nt][j] = 0.f;

    const uint32_t w2b = sb32 + O_W2B;
    const uint32_t w3b = sb32 + O_W3B;

    // ---- fused layers 2+3 over two K/N halves; H2 stays in registers ----
    #pragma unroll
    for (int half = 0; half < 2; half++) {
        const int c0   = half ? 192 : 0;
        const int kb_s = half ? 12 : 0;
        const int kb_e = half ? 25 : 12;
        stage_w2(sb, a, c0, half ? 208 : 192, tid);
        stage_w3(sb, a, c0, half ? 208 : 192, tid);
        __syncthreads();

        for (int kb = kb_s; kb < kb_e; kb++) {
            // layer-2: both 8-col tiles of cols kb*16..+15 via x4 B-loads
            float c0v[4] = {0.f, 0.f, 0.f, 0.f};
            float c1v[4] = {0.f, 0.f, 0.f, 0.f};
            const int nloc = kb * 16 - c0;
            #pragma unroll
            for (int ks = 0; ks < 7; ks++) {
                uint32_t bb[4];
                ldmB4(bb, addrB4(w2b, lane, nloc, ks * 16, P_W2));
                mma16816(c0v, a2f[ks], bb[0], bb[1]);
                mma16816(c1v, a2f[ks], bb[2], bb[3]);
            }
            // epilogue -> layer-3 A fragment (C frag == A frag halves)
            const int cA = kb * 16 + 2 * (lane & 3);
            uint32_t afr[4];
            {
                float g0 = sB2[cA],     g1 = sB2[cA + 1];
                float g2 = sB2[cA + 8], g3 = sB2[cA + 9];
                CVT_BF16X2(afr[0], fmaxf(c0v[0] + g0, 0.f), fmaxf(c0v[1] + g1, 0.f));
                CVT_BF16X2(afr[1], fmaxf(c0v[2] + g0, 0.f), fmaxf(c0v[3] + g1, 0.f));
                CVT_BF16X2(afr[2], fmaxf(c1v[0] + g2, 0.f), fmaxf(c1v[1] + g3, 0.f));
                CVT_BF16X2(afr[3], fmaxf(c1v[2] + g2, 0.f), fmaxf(c1v[3] + g3, 0.f));
            }
            // layer-3: 13 n-tiles, x4 B-loads for pairs
            const int kloc = kb * 16 - c0;
            #pragma unroll
            for (int p = 0; p < 6; p++) {
                uint32_t bb[4];
                ldmB4(bb, addrB4(w3b, lane, p * 16, kloc, P_W3));
                mma16816(acc[2 * p],     afr, bb[0], bb[1]);
                mma16816(acc[2 * p + 1], afr, bb[2], bb[3]);
            }
            {
                uint32_t b0, b1v;
                ldmB2(b0, b1v, addrB2(w3b, lane, 96, kloc, P_W3));
                mma16816(acc[12], afr, b0, b1v);
            }
        }
        __syncthreads();
    }

    // ---- layer-3 epilogue: +b3, relu -> H3 fp32 [256][105] (overlays H1/W2B) ----
    float* H3 = (float*)(sb + O_H1);
    {
        const int r0 = m0 + (lane >> 2);
        #pragma unroll
        for (int nt = 0; nt < 13; nt++) {
            int c = nt * 8 + 2 * (lane & 3);
            if (c < 100) {
                H3[r0 * P_H3 + c]           = fmaxf(acc[nt][0] + sB3[c],     0.f);
                H3[r0 * P_H3 + c + 1]       = fmaxf(acc[nt][1] + sB3[c + 1], 0.f);
                H3[(r0 + 8) * P_H3 + c]     = fmaxf(acc[nt][2] + sB3[c],     0.f);
                H3[(r0 + 8) * P_H3 + c + 1] = fmaxf(acc[nt][3] + sB3[c + 1], 0.f);
            }
        }
    }
    __syncthreads();

    // ---- layer 4 + squared error ----
    float local = 0.f;
    #pragma unroll
    for (int j = 0; j < 3; j++) {
        int o = tid + j * NTHR;
        int r = o & 255, c = o >> 8;
        float s = sB4[c];
        #pragma unroll 4
        for (int k = 0; k < 100; k++) s = fmaf(H3[r * P_H3 + k], sW4[k * 6 + c], s);
        if (r < nrows) { float d = s - sD[r * 6 + c]; local += d * d; }
    }
    #pragma unroll
    for (int off = 16; off; off >>= 1) local += __shfl_xor_sync(0xffffffffu, local, off);
    if (lane == 0) sRed[wid] = local;
    __syncthreads();
    if (tid == 0) {
        float s = 0.f;
        #pragma unroll
        for (int i = 0; i < 16; i++) s += sRed[i];
        atomicAdd(&g_acc, (double)s);
    }
}

__global__ void k_fin(float* out, int n) {
    double acc = g_acc;
    float v = (float)(acc / ((double)NROWS * 6.0));
    for (int i = threadIdx.x; i < n; i += blockDim.x) out[i] = v;
    __syncthreads();
    // reset state for the next sequence (globals start zero at load)
    if (threadIdx.x < NA) g_cnt[threadIdx.x] = 0;
    if (threadIdx.x == NA) g_acc = 0.0;
}

extern "C" void kernel_launch(void* const* d_in, const int* in_sizes, int n_in,
                              void* d_out, int out_size) {
    const float* x  = (const float*)d_in[0];
    const float* nx = (const float*)d_in[1];
    const int*   ac = (const int*)d_in[2];
    const float* W1 = (const float*)d_in[3];
    const float* b1 = (const float*)d_in[4];
    const float* W2 = (const float*)d_in[5];
    const float* b2 = (const float*)d_in[6];
    const float* W3 = (const float*)d_in[7];
    const float* b3 = (const float*)d_in[8];
    const float* W4 = (const float*)d_in[9];
    const float* b4 = (const float*)d_in[10];

    cudaFuncSetAttribute(k_mlp, cudaFuncAttributeMaxDynamicSharedMemorySize, (int)SMEM_REQ);

    k_prep<<<PREP_BLKS + WPREP_BLKS, 256>>>(x, nx, ac, W2, W3);
    k_mlp<<<NA * NT, NTHR, SMEM_REQ>>>(W1, b1, b2, b3, W4, b4);
    k_fin<<<1, 64>>>((float*)d_out, out_size);
}

// round 7
// speedup vs baseline: 5.8878x; 1.1876x over previous
#include <cuda_runtime.h>
#include <cuda_bf16.h>
#include <stdint.h>

#define NROWS 65536
#define XD    362
#define NA    3
#define TILE  256
#define NT    (NROWS / TILE)   // 256
#define NTHR  512

#define P_H1  120   // bf16 pitch, conflict-free ldmatrix
#define P_W2  120
#define P_W3  216
#define P_H3  105   // fp32 pitch, conflict-free layer-4 LDS

// ---------------- device scratch (statically zero at load) ----------------
__device__ float  g_att  [(size_t)NA * NROWS * 6];
__device__ float  g_delta[(size_t)NA * NROWS * 6];
__device__ int    g_cnt[NA];          // reset by k_fin each sequence
__device__ double g_acc;              // reset by k_fin each sequence
__device__ uint4  g_w2t_u4[(size_t)NA * 400 * 14];  // [a][n<400][k<112] bf16
__device__ uint4  g_w3t_u4[(size_t)NA * 104 * 50];  // [a][n<104][k<400] bf16

// ---------------- helpers ----------------
__device__ __forceinline__ uint32_t smem_u32(const void* p) {
    uint32_t a;
    asm("{ .reg .u64 t; cvta.to.shared.u64 t, %1; cvt.u32.u64 %0, t; }" : "=r"(a) : "l"(p));
    return a;
}
#define CVT_BF16X2(res, lo, hi) \
    asm("cvt.rn.bf16x2.f32 %0, %1, %2;" : "=r"(res) : "f"(hi), "f"(lo))

__device__ __forceinline__ void ldmA(uint32_t* a, uint32_t addr) {
    asm volatile("ldmatrix.sync.aligned.m8n8.x4.shared.b16 {%0,%1,%2,%3}, [%4];"
        : "=r"(a[0]), "=r"(a[1]), "=r"(a[2]), "=r"(a[3]) : "r"(addr));
}
__device__ __forceinline__ void ldmB2(uint32_t& b0, uint32_t& b1, uint32_t addr) {
    asm volatile("ldmatrix.sync.aligned.m8n8.x2.shared.b16 {%0,%1}, [%2];"
        : "=r"(b0), "=r"(b1) : "r"(addr));
}
__device__ __forceinline__ void ldmB4(uint32_t* b, uint32_t addr) {
    asm volatile("ldmatrix.sync.aligned.m8n8.x4.shared.b16 {%0,%1,%2,%3}, [%4];"
        : "=r"(b[0]), "=r"(b[1]), "=r"(b[2]), "=r"(b[3]) : "r"(addr));
}
__device__ __forceinline__ void mma16816(float* c, const uint32_t* a, uint32_t b0, uint32_t b1) {
    asm volatile("mma.sync.aligned.m16n8k16.row.col.f32.bf16.bf16.f32 "
        "{%0,%1,%2,%3}, {%4,%5,%6,%7}, {%8,%9}, {%0,%1,%2,%3};"
        : "+f"(c[0]), "+f"(c[1]), "+f"(c[2]), "+f"(c[3])
        : "r"(a[0]), "r"(a[1]), "r"(a[2]), "r"(a[3]), "r"(b0), "r"(b1));
}
__device__ __forceinline__ uint32_t addrA(uint32_t base, int lane, int m0, int k0, int P) {
    int j = lane >> 3;
    int row = m0 + ((j & 1) << 3) + (lane & 7);
    int col = k0 + ((j >> 1) << 3);
    return base + (uint32_t)(row * P + col) * 2u;
}
__device__ __forceinline__ uint32_t addrB2(uint32_t base, int lane, int n0, int k0, int P) {
    int l = lane & 15;
    int row = n0 + (l & 7);
    int col = k0 + ((l >> 3) << 3);
    return base + (uint32_t)(row * P + col) * 2u;
}
__device__ __forceinline__ uint32_t addrB4(uint32_t base, int lane, int n0, int k0, int P) {
    int row = n0 + ((lane >> 4) << 3) + (lane & 7);
    int col = k0 + (((lane >> 3) & 1) << 3);
    return base + (uint32_t)(row * P + col) * 2u;
}

// ---------------- combined prep kernel (1024 threads) ----------------
// blocks [0, NROWS/32): 32 warps x one row each; hierarchical slot assignment
// blocks [NROWS/32, +8): weight transpose/bf16/pad
#define PREP_BLKS (NROWS / 32)
#define WPREP_BLKS 8
#define PTHR 1024

__global__ __launch_bounds__(PTHR)
void k_prep(const float* __restrict__ x, const float* __restrict__ nx,
            const int* __restrict__ act,
            const float* __restrict__ W2, const float* __restrict__ W3) {
    if (blockIdx.x >= PREP_BLKS) {
        int i = (blockIdx.x - PREP_BLKS) * PTHR + threadIdx.x;
        int stride = WPREP_BLKS * PTHR;
        __nv_bfloat16* w2t = (__nv_bfloat16*)g_w2t_u4;
        __nv_bfloat16* w3t = (__nv_bfloat16*)g_w3t_u4;
        for (int t = i; t < NA * 400 * 112; t += stride) {
            int k = t % 112, n = (t / 112) % 400, a = t / (112 * 400);
            float v = (k < 100) ? W2[(size_t)a * 40000 + k * 400 + n] : 0.f;
            w2t[t] = __float2bfloat16(v);
        }
        for (int t = i; t < NA * 104 * 400; t += stride) {
            int k = t % 400, n = (t / 400) % 104, a = t / (400 * 104);
            float v = (n < 100) ? W3[(size_t)a * 40000 + k * 100 + n] : 0.f;
            w3t[t] = __float2bfloat16(v);
        }
        return;
    }

    __shared__ int scnt[NA], sbase[NA];
    const int wid  = threadIdx.x >> 5;
    const int lane = threadIdx.x & 31;
    if (threadIdx.x < NA) scnt[threadIdx.x] = 0;
    __syncthreads();

    const int w = blockIdx.x * 32 + wid;
    const float* xr = x + (size_t)w * XD;

    // prefetch idx<256 in 4 independent loads (covers ~73% of sentinels)
    float2 v0 = *(const float2*)(xr + 2 * lane);
    float2 v1 = *(const float2*)(xr + 2 * lane + 64);
    float2 v2 = *(const float2*)(xr + 2 * lane + 128);
    float2 v3 = *(const float2*)(xr + 2 * lane + 192);
    int found = 0x7fffffff;
    if (v3.y == 10.0f) found = 2 * lane + 193;
    if (v3.x == 10.0f) found = 2 * lane + 192;
    if (v2.y == 10.0f) found = 2 * lane + 129;
    if (v2.x == 10.0f) found = 2 * lane + 128;
    if (v1.y == 10.0f) found = 2 * lane + 65;
    if (v1.x == 10.0f) found = 2 * lane + 64;
    if (v0.y == 10.0f) found = 2 * lane + 1;
    if (v0.x == 10.0f) found = 2 * lane;
    if (!__ballot_sync(0xffffffffu, found != 0x7fffffff)) {
        int i2 = 256 + 2 * lane;
        float2 v4 = *(const float2*)(xr + i2);
        float2 v5 = make_float2(0.f, 0.f);
        if (i2 + 65 < XD) v5 = *(const float2*)(xr + i2 + 64);
        if (v5.y == 10.0f) found = i2 + 65;
        if (v5.x == 10.0f) found = i2 + 64;
        if (v4.y == 10.0f) found = i2 + 1;
        if (v4.x == 10.0f) found = i2;
    }
    #pragma unroll
    for (int off = 16; off; off >>= 1)
        found = min(found, __shfl_xor_sync(0xffffffffu, found, off));
    int p = found;
    if (p < 19 || p >= XD - 19) p = 20;

    const int a = act[w];
    int rank = 0;
    if (lane == 0) rank = atomicAdd(&scnt[a], 1);      // smem: cheap
    __syncthreads();
    if (threadIdx.x < NA)
        sbase[threadIdx.x] = atomicAdd(&g_cnt[threadIdx.x], scnt[threadIdx.x]);  // 3 global atomics/block
    __syncthreads();
    int slot = sbase[a] + rank;
    slot = __shfl_sync(0xffffffffu, slot, 0);

    if (lane < 6) {
        int idx = 0;
        if      (lane == 1) idx = p;
        else if (lane == 2) idx = p - 19;
        else if (lane == 3) idx = p + 19;
        else if (lane == 4) idx = p - 1;
        else if (lane == 5) idx = p + 1;
        float av = xr[idx];
        float nv = nx[(size_t)w * XD + idx];
        size_t o = ((size_t)a * NROWS + (size_t)slot) * 6 + lane;
        g_att[o]   = av;
        g_delta[o] = nv - av;
    }
}

// ---------------- smem layout (bytes) ----------------
#define O_H1   0u         // 256*120*2 = 61440
#define O_W2B  61440u     // 208*120*2 = 49920
#define O_W3B  111360u    // 104*216*2 = 44928
#define O_SX   156288u
#define O_SD   162432u
#define O_W1   168576u
#define O_B1   170976u
#define O_B2   171376u
#define O_B3   172976u
#define O_W4   173376u
#define O_B4   175776u
#define O_RED  175808u
#define SMEM_REQ 175872u
// H3 fp32 [256][105] overlays H1+W2B after both are dead.

__device__ __forceinline__ void stage_w2(char* sb, int a, int c0, int nrow, int tid) {
    const uint4* src = g_w2t_u4 + ((size_t)a * 400 + c0) * 14;
    for (int i = tid; i < nrow * 14; i += NTHR) {
        int n = i / 14, q = i - n * 14;
        *(uint4*)(sb + O_W2B + n * (P_W2 * 2) + q * 16) = src[i];
    }
}
__device__ __forceinline__ void stage_w3(char* sb, int a, int k0, int nk, int tid) {
    const uint4* src = g_w3t_u4 + (size_t)a * 104 * 50 + (k0 >> 3);
    const int nq = nk >> 3;
    for (int i = tid; i < 104 * nq; i += NTHR) {
        int n = i / nq, q = i - n * nq;
        *(uint4*)(sb + O_W3B + n * (P_W3 * 2) + q * 16) = src[n * 50 + q];
    }
}

// ---------------- fused MLP tile kernel ----------------
__global__ __launch_bounds__(NTHR, 1)
void k_mlp(const float* __restrict__ W1, const float* __restrict__ b1,
           const float* __restrict__ b2, const float* __restrict__ b3,
           const float* __restrict__ W4, const float* __restrict__ b4) {
    extern __shared__ char sb[];
    const uint32_t sb32 = smem_u32(sb);

    const int a    = blockIdx.x / NT;
    const int t    = blockIdx.x % NT;
    const int cnt  = g_cnt[a];
    const int row0 = t * TILE;
    if (row0 >= cnt) return;
    const int nrows = min(TILE, cnt - row0);
    const int tid   = threadIdx.x;
    const int wid   = tid >> 5;
    const int lane  = tid & 31;
    const int m0    = wid * 16;

    float* sX  = (float*)(sb + O_SX);
    float* sD  = (float*)(sb + O_SD);
    float* sW1 = (float*)(sb + O_W1);
    float* sB1 = (float*)(sb + O_B1);
    float* sB2 = (float*)(sb + O_B2);
    float* sB3 = (float*)(sb + O_B3);
    float* sW4 = (float*)(sb + O_W4);
    float* sB4 = (float*)(sb + O_B4);
    float* sRed = (float*)(sb + O_RED);

    {   // stage inputs + small weights + HALF-0 big-weight slabs (overlaps layer 1)
        const float* gA = g_att   + ((size_t)a * NROWS + row0) * 6;
        const float* gD = g_delta + ((size_t)a * NROWS + row0) * 6;
        for (int i = tid; i < TILE * 6; i += NTHR) { sX[i] = gA[i]; sD[i] = gD[i]; }
        stage_w2(sb, a, 0, 192, tid);
        stage_w3(sb, a, 0, 192, tid);
        for (int i = tid; i < 600; i += NTHR) sW1[i] = W1[a * 600 + i];
        for (int i = tid; i < 600; i += NTHR) sW4[i] = W4[a * 600 + i];
        for (int i = tid; i < 400; i += NTHR) sB2[i] = b2[a * 400 + i];
        if (tid < 100) sB1[tid] = b1[a * 100 + tid];
        if (tid < 100) sB3[tid] = b3[a * 100 + tid];
        if (tid < 8)   sB4[tid] = (tid < 6) ? b4[a * 6 + tid] : 0.f;
    }
    __syncthreads();

    // ---- layer 1 (fp32) -> H1 bf16 [256][120], zero-pad k 100..119 ----
    {
        const int r = tid & 255;
        const int h = tid >> 8;
        const float* xr = sX + r * 6;
        #pragma unroll
        for (int c = 0; c < 50; c += 2) {
            int j = h * 50 + c;
            float s0 = sB1[j], s1 = sB1[j + 1];
            #pragma unroll
            for (int k = 0; k < 6; k++) {
                s0 = fmaf(xr[k], sW1[k * 100 + j], s0);
                s1 = fmaf(xr[k], sW1[k * 100 + j + 1], s1);
            }
            uint32_t pk; CVT_BF16X2(pk, fmaxf(s0, 0.f), fmaxf(s1, 0.f));
            *(uint32_t*)(sb + O_H1 + (r * P_H1 + j) * 2) = pk;
        }
        if (h == 1) {
            #pragma unroll
            for (int j = 100; j < 120; j += 2)
                *(uint32_t*)(sb + O_H1 + (r * P_H1 + j) * 2) = 0u;
        }
    }
    __syncthreads();

    // cache layer-2 A fragments (persist across both halves)
    uint32_t a2f[7][4];
    #pragma unroll
    for (int ks = 0; ks < 7; ks++)
        ldmA(a2f[ks], addrA(sb32 + O_H1, lane, m0, ks * 16, P_H1));

    // layer-3 accumulators persist across both halves
    float acc[13][4];
    #pragma unroll
    for (int nt = 0; nt < 13; nt++)
        #pragma unroll
        for (int j = 0; j < 4; j++) acc[nt][j] = 0.f;

    const uint32_t w2b = sb32 + O_W2B;
    const uint32_t w3b = sb32 + O_W3B;

    // ---- fused layers 2+3 over two K/N halves; H2 stays in registers ----
    #pragma unroll
    for (int half = 0; half < 2; half++) {
        const int c0   = half ? 192 : 0;
        const int kb_s = half ? 12 : 0;
        const int kb_e = half ? 25 : 12;
        if (half) {   // half-0 slabs staged in the prologue
            __syncthreads();
            stage_w2(sb, a, c0, 208, tid);
            stage_w3(sb, a, c0, 208, tid);
            __syncthreads();
        }

        for (int kb = kb_s; kb < kb_e; kb++) {
            float c0v[4] = {0.f, 0.f, 0.f, 0.f};
            float c1v[4] = {0.f, 0.f, 0.f, 0.f};
            const int nloc = kb * 16 - c0;
            #pragma unroll
            for (int ks = 0; ks < 7; ks++) {
                uint32_t bb[4];
                ldmB4(bb, addrB4(w2b, lane, nloc, ks * 16, P_W2));
                mma16816(c0v, a2f[ks], bb[0], bb[1]);
                mma16816(c1v, a2f[ks], bb[2], bb[3]);
            }
            const int cA = kb * 16 + 2 * (lane & 3);
            uint32_t afr[4];
            {
                float g0 = sB2[cA],     g1 = sB2[cA + 1];
                float g2 = sB2[cA + 8], g3 = sB2[cA + 9];
                CVT_BF16X2(afr[0], fmaxf(c0v[0] + g0, 0.f), fmaxf(c0v[1] + g1, 0.f));
                CVT_BF16X2(afr[1], fmaxf(c0v[2] + g0, 0.f), fmaxf(c0v[3] + g1, 0.f));
                CVT_BF16X2(afr[2], fmaxf(c1v[0] + g2, 0.f), fmaxf(c1v[1] + g3, 0.f));
                CVT_BF16X2(afr[3], fmaxf(c1v[2] + g2, 0.f), fmaxf(c1v[3] + g3, 0.f));
            }
            const int kloc = kb * 16 - c0;
            #pragma unroll
            for (int p = 0; p < 6; p++) {
                uint32_t bb[4];
                ldmB4(bb, addrB4(w3b, lane, p * 16, kloc, P_W3));
                mma16816(acc[2 * p],     afr, bb[0], bb[1]);
                mma16816(acc[2 * p + 1], afr, bb[2], bb[3]);
            }
            {
                uint32_t b0, b1v;
                ldmB2(b0, b1v, addrB2(w3b, lane, 96, kloc, P_W3));
                mma16816(acc[12], afr, b0, b1v);
            }
        }
    }
    __syncthreads();

    // ---- layer-3 epilogue: +b3, relu -> H3 fp32 [256][105] (overlays H1/W2B) ----
    float* H3 = (float*)(sb + O_H1);
    {
        const int r0 = m0 + (lane >> 2);
        #pragma unroll
        for (int nt = 0; nt < 13; nt++) {
            int c = nt * 8 + 2 * (lane & 3);
            if (c < 100) {
                H3[r0 * P_H3 + c]           = fmaxf(acc[nt][0] + sB3[c],     0.f);
                H3[r0 * P_H3 + c + 1]       = fmaxf(acc[nt][1] + sB3[c + 1], 0.f);
                H3[(r0 + 8) * P_H3 + c]     = fmaxf(acc[nt][2] + sB3[c],     0.f);
                H3[(r0 + 8) * P_H3 + c + 1] = fmaxf(acc[nt][3] + sB3[c + 1], 0.f);
            }
        }
    }
    __syncthreads();

    // ---- layer 4 + squared error ----
    float local = 0.f;
    #pragma unroll
    for (int j = 0; j < 3; j++) {
        int o = tid + j * NTHR;
        int r = o & 255, c = o >> 8;
        float s = sB4[c];
        #pragma unroll 4
        for (int k = 0; k < 100; k++) s = fmaf(H3[r * P_H3 + k], sW4[k * 6 + c], s);
        if (r < nrows) { float d = s - sD[r * 6 + c]; local += d * d; }
    }
    #pragma unroll
    for (int off = 16; off; off >>= 1) local += __shfl_xor_sync(0xffffffffu, local, off);
    if (lane == 0) sRed[wid] = local;
    __syncthreads();
    if (tid == 0) {
        float s = 0.f;
        #pragma unroll
        for (int i = 0; i < 16; i++) s += sRed[i];
        atomicAdd(&g_acc, (double)s);
    }
}

__global__ void k_fin(float* out, int n) {
    double acc = g_acc;
    float v = (float)(acc / ((double)NROWS * 6.0));
    for (int i = threadIdx.x; i < n; i += blockDim.x) out[i] = v;
    __syncthreads();
    if (threadIdx.x < NA) g_cnt[threadIdx.x] = 0;
    if (threadIdx.x == NA) g_acc = 0.0;
}

extern "C" void kernel_launch(void* const* d_in, const int* in_sizes, int n_in,
                              void* d_out, int out_size) {
    const float* x  = (const float*)d_in[0];
    const float* nx = (const float*)d_in[1];
    const int*   ac = (const int*)d_in[2];
    const float* W1 = (const float*)d_in[3];
    const float* b1 = (const float*)d_in[4];
    const float* W2 = (const float*)d_in[5];
    const float* b2 = (const float*)d_in[6];
    const float* W3 = (const float*)d_in[7];
    const float* b3 = (const float*)d_in[8];
    const float* W4 = (const float*)d_in[9];
    const float* b4 = (const float*)d_in[10];

    cudaFuncSetAttribute(k_mlp, cudaFuncAttributeMaxDynamicSharedMemorySize, (int)SMEM_REQ);

    k_prep<<<PREP_BLKS + WPREP_BLKS, PTHR>>>(x, nx, ac, W2, W3);
    k_mlp<<<NA * NT, NTHR, SMEM_REQ>>>(W1, b1, b2, b3, W4, b4);
    k_fin<<<1, 64>>>((float*)d_out, out_size);
}